// round 3
// baseline (speedup 1.0000x reference)
#include <cuda_runtime.h>
#include <math.h>

#define DIM      4096
#define BATCH    8192
#define NLAYERS  6
#define EPS      1e-12f
#define MAXNORM  10.0f

// Output layout (fp32, concatenated in reference return order):
//   h_final  : [BATCH, DIM]            offset 0
//   aligns   : [NLAYERS, BATCH, 3]     offset TRACE_A
//   divs     : [NLAYERS, BATCH, 3]     offset TRACE_D
//   tensions : [NLAYERS, BATCH, 3]     offset TRACE_T
#define TRACE_A  ((size_t)BATCH * DIM)
#define TRACE_SZ ((size_t)NLAYERS * BATCH * 3)
#define TRACE_D  (TRACE_A + TRACE_SZ)
#define TRACE_T  (TRACE_D + TRACE_SZ)

__device__ float g_D[9];     // Gram of normalized anchor dirs
__device__ float g_invn[3];  // 1/max(||anchor_k||, eps)

// ---- packed f32x2 helpers (sm_103a FFMA2 path; ptxas never emits these from C++)
typedef unsigned long long ull;

__device__ __forceinline__ ull pk2(float lo, float hi) {
    ull r; asm("mov.b64 %0, {%1, %2};" : "=l"(r) : "f"(lo), "f"(hi)); return r;
}
__device__ __forceinline__ void unpk2(ull v, float& lo, float& hi) {
    asm("mov.b64 {%0, %1}, %2;" : "=f"(lo), "=f"(hi) : "l"(v));
}
__device__ __forceinline__ void fma2(ull& d, ull a, ull b) {
    asm("fma.rn.f32x2 %0, %1, %2, %0;" : "+l"(d) : "l"(a), "l"(b));
}
__device__ __forceinline__ ull mul2(ull a, ull b) {
    ull r; asm("mul.rn.f32x2 %0, %1, %2;" : "=l"(r) : "l"(a), "l"(b)); return r;
}

// ---------------------------------------------------------------------------
// Prep: anchor norms + pairwise dots -> normalized-direction Gram. One block.
// ---------------------------------------------------------------------------
__global__ void prep_kernel(const float* __restrict__ aE,
                            const float* __restrict__ aC,
                            const float* __restrict__ aN) {
    float s[6] = {0.f, 0.f, 0.f, 0.f, 0.f, 0.f};  // EE, CC, NN, EC, EN, CN
    for (int i = threadIdx.x; i < DIM; i += 256) {
        float e = aE[i], c = aC[i], n = aN[i];
        s[0] = fmaf(e, e, s[0]);
        s[1] = fmaf(c, c, s[1]);
        s[2] = fmaf(n, n, s[2]);
        s[3] = fmaf(e, c, s[3]);
        s[4] = fmaf(e, n, s[4]);
        s[5] = fmaf(c, n, s[5]);
    }
    __shared__ float red[8][6];
    int lane = threadIdx.x & 31, w = threadIdx.x >> 5;
#pragma unroll
    for (int j = 0; j < 6; j++)
#pragma unroll
        for (int off = 16; off > 0; off >>= 1)
            s[j] += __shfl_down_sync(0xFFFFFFFFu, s[j], off);
    if (lane == 0)
#pragma unroll
        for (int j = 0; j < 6; j++) red[w][j] = s[j];
    __syncthreads();
    if (threadIdx.x == 0) {
        float t[6];
#pragma unroll
        for (int j = 0; j < 6; j++) {
            float acc = 0.f;
#pragma unroll
            for (int ww = 0; ww < 8; ww++) acc += red[ww][j];
            t[j] = acc;
        }
        float iE = 1.f / fmaxf(sqrtf(t[0]), EPS);
        float iC = 1.f / fmaxf(sqrtf(t[1]), EPS);
        float iN = 1.f / fmaxf(sqrtf(t[2]), EPS);
        g_invn[0] = iE; g_invn[1] = iC; g_invn[2] = iN;
        g_D[0] = t[0] * iE * iE;
        g_D[4] = t[1] * iC * iC;
        g_D[8] = t[2] * iN * iN;
        float ec = t[3] * iE * iC, en = t[4] * iE * iN, cn = t[5] * iC * iN;
        g_D[1] = ec; g_D[3] = ec;
        g_D[2] = en; g_D[6] = en;
        g_D[5] = cn; g_D[7] = cn;
    }
}

// ---------------------------------------------------------------------------
// Main: one block (256 thr) per row. Row held in REGISTERS (4x ulonglong2
// = 8 packed f32 pairs) across the scalar recurrence; packed f32x2 FMAs in
// both passes. No smem row stash.
// ---------------------------------------------------------------------------
__global__ __launch_bounds__(256, 4) void collapse_kernel(
    const float* __restrict__ h0,
    const float* __restrict__ aE,
    const float* __restrict__ aC,
    const float* __restrict__ aN,
    float* __restrict__ out)
{
    const int b   = blockIdx.x;
    const int tid = threadIdx.x;

    __shared__ float sred[8 * 4];
    __shared__ float ssum[4];

    const ulonglong2* hr = (const ulonglong2*)(h0 + (size_t)b * DIM);
    const ulonglong2* e2 = (const ulonglong2*)aE;
    const ulonglong2* c2 = (const ulonglong2*)aC;
    const ulonglong2* n2 = (const ulonglong2*)aN;

    // ---- pass 1: 4 fused dot products, packed ----
    ulonglong2 hv[4];
    ull aH = 0ull, aE_ = 0ull, aC_ = 0ull, aN_ = 0ull;  // packed (0.f,0.f)
#pragma unroll
    for (int it = 0; it < 4; it++) {
        int i = it * 256 + tid;
        ulonglong2 h = hr[i];
        hv[it] = h;
        ulonglong2 e = e2[i], c = c2[i], n = n2[i];
        fma2(aH, h.x, h.x);  fma2(aH, h.y, h.y);
        fma2(aE_, h.x, e.x); fma2(aE_, h.y, e.y);
        fma2(aC_, h.x, c.x); fma2(aC_, h.y, c.y);
        fma2(aN_, h.x, n.x); fma2(aN_, h.y, n.y);
    }
    float v0, v1, v2, v3, lo, hi;
    unpk2(aH, lo, hi);  v0 = lo + hi;
    unpk2(aE_, lo, hi); v1 = lo + hi;
    unpk2(aC_, lo, hi); v2 = lo + hi;
    unpk2(aN_, lo, hi); v3 = lo + hi;

    // ---- block reduce 4 partials ----
#pragma unroll
    for (int off = 16; off > 0; off >>= 1) {
        v0 += __shfl_down_sync(0xFFFFFFFFu, v0, off);
        v1 += __shfl_down_sync(0xFFFFFFFFu, v1, off);
        v2 += __shfl_down_sync(0xFFFFFFFFu, v2, off);
        v3 += __shfl_down_sync(0xFFFFFFFFu, v3, off);
    }
    {
        int lane = tid & 31, w = tid >> 5;
        if (lane == 0) {
            sred[w * 4 + 0] = v0; sred[w * 4 + 1] = v1;
            sred[w * 4 + 2] = v2; sred[w * 4 + 3] = v3;
        }
    }
    __syncthreads();
    if (tid < 4) {
        float acc = 0.f;
#pragma unroll
        for (int ww = 0; ww < 8; ww++) acc += sred[ww * 4 + tid];
        ssum[tid] = acc;
    }
    __syncthreads();

    // ---- scalar 6-layer recurrence over span coefficients (uniform) ----
    const float g00   = ssum[0];
    const float invn0 = g_invn[0], invn1 = g_invn[1], invn2 = g_invn[2];
    float g0[3] = { ssum[1] * invn0, ssum[2] * invn1, ssum[3] * invn2 };
    float D[9];
#pragma unroll
    for (int j = 0; j < 9; j++) D[j] = g_D[j];

    float c0 = 1.f;
    float cc[3] = { 0.f, 0.f, 0.f };
    const float str[3] = { 0.1f, 0.1f, 0.05f };

#pragma unroll
    for (int l = 0; l < NLAYERS; l++) {
        float hd[3];
#pragma unroll
        for (int k = 0; k < 3; k++)
            hd[k] = c0 * g0[k] + cc[0] * D[0 * 3 + k] + cc[1] * D[1 * 3 + k] + cc[2] * D[2 * 3 + k];
        float hh = c0 * (c0 * g00 + cc[0] * g0[0] + cc[1] * g0[1] + cc[2] * g0[2])
                 + cc[0] * hd[0] + cc[1] * hd[1] + cc[2] * hd[2];
        float inv = 1.f / fmaxf(sqrtf(hh), EPS);

        float a[3];
#pragma unroll
        for (int k = 0; k < 3; k++) {
            float align = hd[k] * inv;
            float dv    = 1.f - align;
            float tens  = fmaxf(dv, 0.f);
            if (tid == 0) {
                size_t ti = (size_t)l * (BATCH * 3) + (size_t)b * 3 + k;
                out[TRACE_A + ti] = align;
                out[TRACE_D + ti] = dv;
                out[TRACE_T + ti] = tens;
            }
            float msq = hh - 2.f * hd[k] + D[k * 3 + k];
            float m   = sqrtf(fmaxf(msq, 0.f));
            a[k] = str[k] * dv / fmaxf(m, EPS);
        }
        float f = 1.f - (a[0] + a[1] + a[2]);
        c0 *= f;
        cc[0] = cc[0] * f + a[0];
        cc[1] = cc[1] * f + a[1];
        cc[2] = cc[2] * f + a[2];

        float hd2[3];
#pragma unroll
        for (int k = 0; k < 3; k++)
            hd2[k] = c0 * g0[k] + cc[0] * D[0 * 3 + k] + cc[1] * D[1 * 3 + k] + cc[2] * D[2 * 3 + k];
        float hh2 = c0 * (c0 * g00 + cc[0] * g0[0] + cc[1] * g0[1] + cc[2] * g0[2])
                  + cc[0] * hd2[0] + cc[1] * hd2[1] + cc[2] * hd2[2];
        float nn = sqrtf(hh2);
        if (nn > MAXNORM) {
            float scl = MAXNORM / (nn + 1e-8f);
            c0 *= scl; cc[0] *= scl; cc[1] *= scl; cc[2] *= scl;
        }
    }

    // ---- pass 2: h_final = c0*h + wE*E + wC*C + wN*N (h from registers) ----
    float wE = cc[0] * invn0, wC = cc[1] * invn1, wN = cc[2] * invn2;
    ull c0p = pk2(c0, c0), wEp = pk2(wE, wE), wCp = pk2(wC, wC), wNp = pk2(wN, wN);

    ulonglong2* orow = (ulonglong2*)(out + (size_t)b * DIM);
#pragma unroll
    for (int it = 0; it < 4; it++) {
        int i = it * 256 + tid;
        ulonglong2 e = e2[i], c = c2[i], n = n2[i];
        ull o0 = mul2(c0p, hv[it].x);
        fma2(o0, wEp, e.x); fma2(o0, wCp, c.x); fma2(o0, wNp, n.x);
        ull o1 = mul2(c0p, hv[it].y);
        fma2(o1, wEp, e.y); fma2(o1, wCp, c.y); fma2(o1, wNp, n.y);
        ulonglong2 o; o.x = o0; o.y = o1;
        orow[i] = o;
    }
}

extern "C" void kernel_launch(void* const* d_in, const int* in_sizes, int n_in,
                              void* d_out, int out_size) {
    const float* h0 = (const float*)d_in[0];
    const float* aE = (const float*)d_in[1];
    const float* aC = (const float*)d_in[2];
    const float* aN = (const float*)d_in[3];
    float* out = (float*)d_out;

    prep_kernel<<<1, 256>>>(aE, aC, aN);
    collapse_kernel<<<BATCH, 256>>>(h0, aE, aC, aN, out);
}

// round 4
// speedup vs baseline: 1.0577x; 1.0577x over previous
#include <cuda_runtime.h>
#include <math.h>

#define DIM      4096
#define BATCH    8192
#define NLAYERS  6
#define EPS      1e-12f
#define MAXNORM  10.0f

// Output layout (fp32, concatenated in reference return order):
//   h_final  : [BATCH, DIM]            offset 0
//   aligns   : [NLAYERS, BATCH, 3]     offset TRACE_A
//   divs     : [NLAYERS, BATCH, 3]     offset TRACE_D
//   tensions : [NLAYERS, BATCH, 3]     offset TRACE_T
#define TRACE_A  ((size_t)BATCH * DIM)
#define TRACE_SZ ((size_t)NLAYERS * BATCH * 3)
#define TRACE_D  (TRACE_A + TRACE_SZ)
#define TRACE_T  (TRACE_D + TRACE_SZ)

__device__ float g_D[9];     // Gram of normalized anchor dirs
__device__ float g_invn[3];  // 1/max(||anchor_k||, eps)

// ---------------------------------------------------------------------------
// Prep: anchor norms + pairwise dots -> normalized-direction Gram. One block.
// ---------------------------------------------------------------------------
__global__ void prep_kernel(const float* __restrict__ aE,
                            const float* __restrict__ aC,
                            const float* __restrict__ aN) {
    float s[6] = {0.f, 0.f, 0.f, 0.f, 0.f, 0.f};  // EE, CC, NN, EC, EN, CN
    for (int i = threadIdx.x; i < DIM; i += 256) {
        float e = aE[i], c = aC[i], n = aN[i];
        s[0] = fmaf(e, e, s[0]);
        s[1] = fmaf(c, c, s[1]);
        s[2] = fmaf(n, n, s[2]);
        s[3] = fmaf(e, c, s[3]);
        s[4] = fmaf(e, n, s[4]);
        s[5] = fmaf(c, n, s[5]);
    }
    __shared__ float red[8][6];
    int lane = threadIdx.x & 31, w = threadIdx.x >> 5;
#pragma unroll
    for (int j = 0; j < 6; j++)
#pragma unroll
        for (int off = 16; off > 0; off >>= 1)
            s[j] += __shfl_down_sync(0xFFFFFFFFu, s[j], off);
    if (lane == 0)
#pragma unroll
        for (int j = 0; j < 6; j++) red[w][j] = s[j];
    __syncthreads();
    if (threadIdx.x == 0) {
        float t[6];
#pragma unroll
        for (int j = 0; j < 6; j++) {
            float acc = 0.f;
#pragma unroll
            for (int ww = 0; ww < 8; ww++) acc += red[ww][j];
            t[j] = acc;
        }
        float iE = 1.f / fmaxf(sqrtf(t[0]), EPS);
        float iC = 1.f / fmaxf(sqrtf(t[1]), EPS);
        float iN = 1.f / fmaxf(sqrtf(t[2]), EPS);
        g_invn[0] = iE; g_invn[1] = iC; g_invn[2] = iN;
        g_D[0] = t[0] * iE * iE;
        g_D[4] = t[1] * iC * iC;
        g_D[8] = t[2] * iN * iN;
        float ec = t[3] * iE * iC, en = t[4] * iE * iN, cn = t[5] * iC * iN;
        g_D[1] = ec; g_D[3] = ec;
        g_D[2] = en; g_D[6] = en;
        g_D[5] = cn; g_D[7] = cn;
    }
}

// ---------------------------------------------------------------------------
// Main: one block (256 thr) per row.
//   Pass 1: fused dots (h.h, h.anchor_k), row stashed in 16 KB smem.
//   Scalar 6-layer recurrence: WARP 0 ONLY (block-uniform values) —
//   other 7 warps wait at the barrier instead of redundantly issuing
//   ~450 instructions each. Coeffs broadcast via smem.
//   Pass 2: h_final = c0*h + wE*E + wC*C + wN*N from smem + L1-hit anchors.
// ---------------------------------------------------------------------------
__global__ __launch_bounds__(256, 4) void collapse_kernel(
    const float* __restrict__ h0,
    const float* __restrict__ aE,
    const float* __restrict__ aC,
    const float* __restrict__ aN,
    float* __restrict__ out)
{
    const int b   = blockIdx.x;
    const int tid = threadIdx.x;

    __shared__ float4 sh[DIM / 4];     // 16 KB row stash
    __shared__ float  sred[8 * 4];     // per-warp partials
    __shared__ float  scoef[4];        // broadcast: c0, wE, wC, wN

    const float4* hr = (const float4*)(h0 + (size_t)b * DIM);
    const float4* e4 = (const float4*)aE;
    const float4* c4 = (const float4*)aC;
    const float4* n4 = (const float4*)aN;

    // ---- pass 1: 4 fused dot products ----
    float shh = 0.f, sE = 0.f, sC = 0.f, sN = 0.f;
#pragma unroll
    for (int it = 0; it < DIM / 4 / 256; it++) {
        int i = it * 256 + tid;
        float4 h = hr[i];
        sh[i] = h;
        float4 e = e4[i], c = c4[i], n = n4[i];
        shh = fmaf(h.x, h.x, fmaf(h.y, h.y, fmaf(h.z, h.z, fmaf(h.w, h.w, shh))));
        sE  = fmaf(h.x, e.x, fmaf(h.y, e.y, fmaf(h.z, e.z, fmaf(h.w, e.w, sE))));
        sC  = fmaf(h.x, c.x, fmaf(h.y, c.y, fmaf(h.z, c.z, fmaf(h.w, c.w, sC))));
        sN  = fmaf(h.x, n.x, fmaf(h.y, n.y, fmaf(h.z, n.z, fmaf(h.w, n.w, sN))));
    }

    // ---- warp-level reduce, stash per-warp partials ----
    {
        float v0 = shh, v1 = sE, v2 = sC, v3 = sN;
#pragma unroll
        for (int off = 16; off > 0; off >>= 1) {
            v0 += __shfl_down_sync(0xFFFFFFFFu, v0, off);
            v1 += __shfl_down_sync(0xFFFFFFFFu, v1, off);
            v2 += __shfl_down_sync(0xFFFFFFFFu, v2, off);
            v3 += __shfl_down_sync(0xFFFFFFFFu, v3, off);
        }
        int lane = tid & 31, w = tid >> 5;
        if (lane == 0) {
            sred[w * 4 + 0] = v0; sred[w * 4 + 1] = v1;
            sred[w * 4 + 2] = v2; sred[w * 4 + 3] = v3;
        }
    }
    __syncthreads();

    // ---- warp 0 only: final reduce + scalar 6-layer recurrence ----
    if (tid < 32) {
        // lanes 0-3 sum the 8 warp partials, then broadcast to whole warp
        float acc = 0.f;
        if (tid < 4) {
#pragma unroll
            for (int ww = 0; ww < 8; ww++) acc += sred[ww * 4 + tid];
        }
        float g00 = __shfl_sync(0xFFFFFFFFu, acc, 0);
        float sE_ = __shfl_sync(0xFFFFFFFFu, acc, 1);
        float sC_ = __shfl_sync(0xFFFFFFFFu, acc, 2);
        float sN_ = __shfl_sync(0xFFFFFFFFu, acc, 3);

        const float invn0 = g_invn[0], invn1 = g_invn[1], invn2 = g_invn[2];
        float g0[3] = { sE_ * invn0, sC_ * invn1, sN_ * invn2 };
        float D[9];
#pragma unroll
        for (int j = 0; j < 9; j++) D[j] = g_D[j];

        float c0 = 1.f;
        float cc[3] = { 0.f, 0.f, 0.f };
        const float str[3] = { 0.1f, 0.1f, 0.05f };

#pragma unroll
        for (int l = 0; l < NLAYERS; l++) {
            float hd[3];
#pragma unroll
            for (int k = 0; k < 3; k++)
                hd[k] = c0 * g0[k] + cc[0] * D[0 * 3 + k] + cc[1] * D[1 * 3 + k] + cc[2] * D[2 * 3 + k];
            float hh = c0 * (c0 * g00 + cc[0] * g0[0] + cc[1] * g0[1] + cc[2] * g0[2])
                     + cc[0] * hd[0] + cc[1] * hd[1] + cc[2] * hd[2];
            float inv = 1.f / fmaxf(sqrtf(hh), EPS);

            float a[3];
#pragma unroll
            for (int k = 0; k < 3; k++) {
                float align = hd[k] * inv;
                float dv    = 1.f - align;
                float tens  = fmaxf(dv, 0.f);
                if (tid == 0) {
                    size_t ti = (size_t)l * (BATCH * 3) + (size_t)b * 3 + k;
                    out[TRACE_A + ti] = align;
                    out[TRACE_D + ti] = dv;
                    out[TRACE_T + ti] = tens;
                }
                float msq = hh - 2.f * hd[k] + D[k * 3 + k];
                float m   = sqrtf(fmaxf(msq, 0.f));
                a[k] = str[k] * dv / fmaxf(m, EPS);
            }
            float f = 1.f - (a[0] + a[1] + a[2]);
            c0 *= f;
            cc[0] = cc[0] * f + a[0];
            cc[1] = cc[1] * f + a[1];
            cc[2] = cc[2] * f + a[2];

            // recompute ||h_new|| via Gram quadratic form, apply clamp
            float hd2[3];
#pragma unroll
            for (int k = 0; k < 3; k++)
                hd2[k] = c0 * g0[k] + cc[0] * D[0 * 3 + k] + cc[1] * D[1 * 3 + k] + cc[2] * D[2 * 3 + k];
            float hh2 = c0 * (c0 * g00 + cc[0] * g0[0] + cc[1] * g0[1] + cc[2] * g0[2])
                      + cc[0] * hd2[0] + cc[1] * hd2[1] + cc[2] * hd2[2];
            float nn = sqrtf(hh2);
            if (nn > MAXNORM) {
                float scl = MAXNORM / (nn + 1e-8f);
                c0 *= scl; cc[0] *= scl; cc[1] *= scl; cc[2] *= scl;
            }
        }

        if (tid == 0) {
            scoef[0] = c0;
            scoef[1] = cc[0] * invn0;
            scoef[2] = cc[1] * invn1;
            scoef[3] = cc[2] * invn2;
        }
    }
    __syncthreads();

    // ---- pass 2: materialize h_final ----
    const float c0 = scoef[0], wE = scoef[1], wC = scoef[2], wN = scoef[3];
    float4* orow = (float4*)(out + (size_t)b * DIM);
#pragma unroll
    for (int it = 0; it < DIM / 4 / 256; it++) {
        int i = it * 256 + tid;
        float4 h = sh[i];
        float4 e = e4[i], c = c4[i], n = n4[i];
        float4 o;
        o.x = fmaf(c0, h.x, fmaf(wE, e.x, fmaf(wC, c.x, wN * n.x)));
        o.y = fmaf(c0, h.y, fmaf(wE, e.y, fmaf(wC, c.y, wN * n.y)));
        o.z = fmaf(c0, h.z, fmaf(wE, e.z, fmaf(wC, c.z, wN * n.z)));
        o.w = fmaf(c0, h.w, fmaf(wE, e.w, fmaf(wC, c.w, wN * n.w)));
        orow[i] = o;
    }
}

extern "C" void kernel_launch(void* const* d_in, const int* in_sizes, int n_in,
                              void* d_out, int out_size) {
    const float* h0 = (const float*)d_in[0];
    const float* aE = (const float*)d_in[1];
    const float* aC = (const float*)d_in[2];
    const float* aN = (const float*)d_in[3];
    float* out = (float*)d_out;

    prep_kernel<<<1, 256>>>(aE, aC, aN);
    collapse_kernel<<<BATCH, 256>>>(h0, aE, aC, aN, out);
}

// round 9
// speedup vs baseline: 1.6248x; 1.5361x over previous
#include <cuda_runtime.h>
#include <math.h>

#define DIM      4096
#define BATCH    8192
#define NLAYERS  6
#define EPS      1e-12f
#define MAXNORM  10.0f

// Output layout (fp32, concatenated in reference return order):
//   h_final  : [BATCH, DIM]            offset 0
//   aligns   : [NLAYERS, BATCH, 3]     offset TRACE_A
//   divs     : [NLAYERS, BATCH, 3]     offset TRACE_D
//   tensions : [NLAYERS, BATCH, 3]     offset TRACE_T
#define TRACE_A  ((size_t)BATCH * DIM)
#define TRACE_SZ ((size_t)NLAYERS * BATCH * 3)
#define TRACE_D  (TRACE_A + TRACE_SZ)
#define TRACE_T  (TRACE_D + TRACE_SZ)

__device__ float g_D[9];     // Gram of normalized anchor dirs
__device__ float g_invn[3];  // 1/max(||anchor_k||, eps)

// ---------------------------------------------------------------------------
// Prep: anchor norms + pairwise dots -> normalized-direction Gram. One block.
// ---------------------------------------------------------------------------
__global__ void prep_kernel(const float* __restrict__ aE,
                            const float* __restrict__ aC,
                            const float* __restrict__ aN) {
    float s[6] = {0.f, 0.f, 0.f, 0.f, 0.f, 0.f};  // EE, CC, NN, EC, EN, CN
    for (int i = threadIdx.x; i < DIM; i += 256) {
        float e = aE[i], c = aC[i], n = aN[i];
        s[0] = fmaf(e, e, s[0]);
        s[1] = fmaf(c, c, s[1]);
        s[2] = fmaf(n, n, s[2]);
        s[3] = fmaf(e, c, s[3]);
        s[4] = fmaf(e, n, s[4]);
        s[5] = fmaf(c, n, s[5]);
    }
    __shared__ float red[8][6];
    int lane = threadIdx.x & 31, w = threadIdx.x >> 5;
#pragma unroll
    for (int j = 0; j < 6; j++)
#pragma unroll
        for (int off = 16; off > 0; off >>= 1)
            s[j] += __shfl_down_sync(0xFFFFFFFFu, s[j], off);
    if (lane == 0)
#pragma unroll
        for (int j = 0; j < 6; j++) red[w][j] = s[j];
    __syncthreads();
    if (threadIdx.x == 0) {
        float t[6];
#pragma unroll
        for (int j = 0; j < 6; j++) {
            float acc = 0.f;
#pragma unroll
            for (int ww = 0; ww < 8; ww++) acc += red[ww][j];
            t[j] = acc;
        }
        float iE = 1.f / fmaxf(sqrtf(t[0]), EPS);
        float iC = 1.f / fmaxf(sqrtf(t[1]), EPS);
        float iN = 1.f / fmaxf(sqrtf(t[2]), EPS);
        g_invn[0] = iE; g_invn[1] = iC; g_invn[2] = iN;
        g_D[0] = t[0] * iE * iE;
        g_D[4] = t[1] * iC * iC;
        g_D[8] = t[2] * iN * iN;
        float ec = t[3] * iE * iC, en = t[4] * iE * iN, cn = t[5] * iC * iN;
        g_D[1] = ec; g_D[3] = ec;
        g_D[2] = en; g_D[6] = en;
        g_D[5] = cn; g_D[7] = cn;
    }
}

// Scalar 6-layer recurrence: executed redundantly by one full warp per row.
// MUFU-only (rsqrtf) — no sqrt.rn / div.rn NR sequences on the chain.
// lane0 writes the 54 trace scalars. Returns (c0, wE, wC, wN).
__device__ __forceinline__ void run_recurrence(
    float g00, float sE_, float sC_, float sN_,
    int row, float* __restrict__ out, int lane, float4& coef)
{
    const float invn0 = g_invn[0], invn1 = g_invn[1], invn2 = g_invn[2];
    float g0[3] = { sE_ * invn0, sC_ * invn1, sN_ * invn2 };
    float D[9];
#pragma unroll
    for (int j = 0; j < 9; j++) D[j] = g_D[j];

    float c0 = 1.f;
    float cc[3] = { 0.f, 0.f, 0.f };
    const float str[3] = { 0.1f, 0.1f, 0.05f };

#pragma unroll
    for (int l = 0; l < NLAYERS; l++) {
        float hd[3];
#pragma unroll
        for (int k = 0; k < 3; k++)
            hd[k] = c0 * g0[k] + cc[0] * D[0 * 3 + k] + cc[1] * D[1 * 3 + k] + cc[2] * D[2 * 3 + k];
        float hh = c0 * (c0 * g00 + cc[0] * g0[0] + cc[1] * g0[1] + cc[2] * g0[2])
                 + cc[0] * hd[0] + cc[1] * hd[1] + cc[2] * hd[2];
        float inv = rsqrtf(fmaxf(hh, 1e-24f));   // 1/||h||

        float a[3];
#pragma unroll
        for (int k = 0; k < 3; k++) {
            float align = hd[k] * inv;
            float dv    = 1.f - align;
            float tens  = fmaxf(dv, 0.f);
            if (lane == 0) {
                size_t ti = (size_t)l * (BATCH * 3) + (size_t)row * 3 + k;
                out[TRACE_A + ti] = align;
                out[TRACE_D + ti] = dv;
                out[TRACE_T + ti] = tens;
            }
            float msq = fmaxf(hh - 2.f * hd[k] + D[k * 3 + k], 1e-24f);
            a[k] = str[k] * dv * rsqrtf(msq);    // str*dv/||h - dir_k||
        }
        float f = 1.f - (a[0] + a[1] + a[2]);
        c0 *= f;
        cc[0] = cc[0] * f + a[0];
        cc[1] = cc[1] * f + a[1];
        cc[2] = cc[2] * f + a[2];

        // ||h_new|| via Gram quadratic form; clamp to MAXNORM
        float hd2[3];
#pragma unroll
        for (int k = 0; k < 3; k++)
            hd2[k] = c0 * g0[k] + cc[0] * D[0 * 3 + k] + cc[1] * D[1 * 3 + k] + cc[2] * D[2 * 3 + k];
        float hh2 = c0 * (c0 * g00 + cc[0] * g0[0] + cc[1] * g0[1] + cc[2] * g0[2])
                  + cc[0] * hd2[0] + cc[1] * hd2[1] + cc[2] * hd2[2];
        float rn = rsqrtf(fmaxf(hh2, 1e-24f));
        float nn = hh2 * rn;                     // ||h_new||
        if (nn > MAXNORM) {
            float scl = MAXNORM * rn;            // 10/||h||  (1e-8 additive is below fp32 eps at 10)
            c0 *= scl; cc[0] *= scl; cc[1] *= scl; cc[2] *= scl;
        }
    }
    coef.x = c0;
    coef.y = cc[0] * invn0;
    coef.z = cc[1] * invn1;
    coef.w = cc[2] * invn2;
}

// ---------------------------------------------------------------------------
// Main: one block (256 thr) per TWO rows. Anchors loaded once per iteration
// and applied to both rows (halves dominant L1 traffic). Warp 0 / warp 1 run
// the two rows' scalar recurrences concurrently (MUFU-shortened chain).
// ---------------------------------------------------------------------------
__global__ __launch_bounds__(256, 4) void collapse_kernel(
    const float* __restrict__ h0,
    const float* __restrict__ aE,
    const float* __restrict__ aC,
    const float* __restrict__ aN,
    float* __restrict__ out)
{
    const int b0  = blockIdx.x * 2;       // first of the two rows
    const int tid = threadIdx.x;

    __shared__ float4 sh0[DIM / 4];       // 16 KB row 0
    __shared__ float4 sh1[DIM / 4];       // 16 KB row 1
    __shared__ float  sred[8 * 8];        // per-warp partials (2 rows x 4 dots)
    __shared__ float4 scoef[2];           // broadcast coeffs per row

    const float4* hr0 = (const float4*)(h0 + (size_t)b0 * DIM);
    const float4* hr1 = (const float4*)(h0 + (size_t)(b0 + 1) * DIM);
    const float4* e4  = (const float4*)aE;
    const float4* c4  = (const float4*)aC;
    const float4* n4  = (const float4*)aN;

    // ---- pass 1: 8 fused dot products (4 per row), anchors loaded once ----
    float p0h = 0.f, p0E = 0.f, p0C = 0.f, p0N = 0.f;
    float p1h = 0.f, p1E = 0.f, p1C = 0.f, p1N = 0.f;
#pragma unroll
    for (int it = 0; it < DIM / 4 / 256; it++) {
        int i = it * 256 + tid;
        float4 e = e4[i], c = c4[i], n = n4[i];
        float4 ha = hr0[i]; sh0[i] = ha;
        float4 hb = hr1[i]; sh1[i] = hb;
        p0h = fmaf(ha.x, ha.x, fmaf(ha.y, ha.y, fmaf(ha.z, ha.z, fmaf(ha.w, ha.w, p0h))));
        p0E = fmaf(ha.x, e.x, fmaf(ha.y, e.y, fmaf(ha.z, e.z, fmaf(ha.w, e.w, p0E))));
        p0C = fmaf(ha.x, c.x, fmaf(ha.y, c.y, fmaf(ha.z, c.z, fmaf(ha.w, c.w, p0C))));
        p0N = fmaf(ha.x, n.x, fmaf(ha.y, n.y, fmaf(ha.z, n.z, fmaf(ha.w, n.w, p0N))));
        p1h = fmaf(hb.x, hb.x, fmaf(hb.y, hb.y, fmaf(hb.z, hb.z, fmaf(hb.w, hb.w, p1h))));
        p1E = fmaf(hb.x, e.x, fmaf(hb.y, e.y, fmaf(hb.z, e.z, fmaf(hb.w, e.w, p1E))));
        p1C = fmaf(hb.x, c.x, fmaf(hb.y, c.y, fmaf(hb.z, c.z, fmaf(hb.w, c.w, p1C))));
        p1N = fmaf(hb.x, n.x, fmaf(hb.y, n.y, fmaf(hb.z, n.z, fmaf(hb.w, n.w, p1N))));
    }

    // ---- warp-level reduce, stash per-warp partials ----
    {
#pragma unroll
        for (int off = 16; off > 0; off >>= 1) {
            p0h += __shfl_down_sync(0xFFFFFFFFu, p0h, off);
            p0E += __shfl_down_sync(0xFFFFFFFFu, p0E, off);
            p0C += __shfl_down_sync(0xFFFFFFFFu, p0C, off);
            p0N += __shfl_down_sync(0xFFFFFFFFu, p0N, off);
            p1h += __shfl_down_sync(0xFFFFFFFFu, p1h, off);
            p1E += __shfl_down_sync(0xFFFFFFFFu, p1E, off);
            p1C += __shfl_down_sync(0xFFFFFFFFu, p1C, off);
            p1N += __shfl_down_sync(0xFFFFFFFFu, p1N, off);
        }
        int lane = tid & 31, w = tid >> 5;
        if (lane == 0) {
            float* dst = &sred[w * 8];
            dst[0] = p0h; dst[1] = p0E; dst[2] = p0C; dst[3] = p0N;
            dst[4] = p1h; dst[5] = p1E; dst[6] = p1C; dst[7] = p1N;
        }
    }
    __syncthreads();

    // ---- warps 0,1: final reduce + scalar recurrence (one row each) ----
    const int wid = tid >> 5;
    if (wid < 2) {
        int lane = tid & 31;
        float acc = 0.f;
        if (lane < 4) {
            int j = wid * 4 + lane;
#pragma unroll
            for (int ww = 0; ww < 8; ww++) acc += sred[ww * 8 + j];
        }
        float g00 = __shfl_sync(0xFFFFFFFFu, acc, 0);
        float sE_ = __shfl_sync(0xFFFFFFFFu, acc, 1);
        float sC_ = __shfl_sync(0xFFFFFFFFu, acc, 2);
        float sN_ = __shfl_sync(0xFFFFFFFFu, acc, 3);

        float4 coef;
        run_recurrence(g00, sE_, sC_, sN_, b0 + wid, out, lane, coef);
        if (lane == 0) scoef[wid] = coef;
    }
    __syncthreads();

    // ---- pass 2: materialize both rows, anchors loaded once ----
    const float4 k0 = scoef[0];
    const float4 k1 = scoef[1];
    float4* o0 = (float4*)(out + (size_t)b0 * DIM);
    float4* o1 = (float4*)(out + (size_t)(b0 + 1) * DIM);
#pragma unroll
    for (int it = 0; it < DIM / 4 / 256; it++) {
        int i = it * 256 + tid;
        float4 e = e4[i], c = c4[i], n = n4[i];
        float4 ha = sh0[i];
        float4 hb = sh1[i];
        float4 oa, ob;
        oa.x = fmaf(k0.x, ha.x, fmaf(k0.y, e.x, fmaf(k0.z, c.x, k0.w * n.x)));
        oa.y = fmaf(k0.x, ha.y, fmaf(k0.y, e.y, fmaf(k0.z, c.y, k0.w * n.y)));
        oa.z = fmaf(k0.x, ha.z, fmaf(k0.y, e.z, fmaf(k0.z, c.z, k0.w * n.z)));
        oa.w = fmaf(k0.x, ha.w, fmaf(k0.y, e.w, fmaf(k0.z, c.w, k0.w * n.w)));
        ob.x = fmaf(k1.x, hb.x, fmaf(k1.y, e.x, fmaf(k1.z, c.x, k1.w * n.x)));
        ob.y = fmaf(k1.x, hb.y, fmaf(k1.y, e.y, fmaf(k1.z, c.y, k1.w * n.y)));
        ob.z = fmaf(k1.x, hb.z, fmaf(k1.y, e.z, fmaf(k1.z, c.z, k1.w * n.z)));
        ob.w = fmaf(k1.x, hb.w, fmaf(k1.y, e.w, fmaf(k1.z, c.w, k1.w * n.w)));
        o0[i] = oa;
        o1[i] = ob;
    }
}

extern "C" void kernel_launch(void* const* d_in, const int* in_sizes, int n_in,
                              void* d_out, int out_size) {
    const float* h0 = (const float*)d_in[0];
    const float* aE = (const float*)d_in[1];
    const float* aC = (const float*)d_in[2];
    const float* aN = (const float*)d_in[3];
    float* out = (float*)d_out;

    prep_kernel<<<1, 256>>>(aE, aC, aN);
    collapse_kernel<<<BATCH / 2, 256>>>(h0, aE, aC, aN, out);
}